// round 5
// baseline (speedup 1.0000x reference)
#include <cuda_runtime.h>

#define EPSV 1e-7f
#define NPOS 288     // 2*12*12 output positions
#define KKI  288     // 3*3*32 input votes
#define NC   32
#define NTH  256
#define NWARP 8
#define IPW  36      // KKI / NWARP

typedef unsigned long long u64;

// Packed f32x2 ops (Blackwell sm_103a)
#define FMA2(d, a, b, c_) asm("fma.rn.f32x2 %0, %1, %2, %3;" : "=l"(d) : "l"(a), "l"(b), "l"(c_))
#define MUL2(d, a, b)     asm("mul.rn.f32x2 %0, %1, %2;"     : "=l"(d) : "l"(a), "l"(b))
#define ADD2(d, a, b)     asm("add.rn.f32x2 %0, %1, %2;"     : "=l"(d) : "l"(a), "l"(b))
#define PACK2(d, lo, hi)  asm("mov.b64 %0, {%1, %2};" : "=l"(d) : "r"(__float_as_uint(lo)), "r"(__float_as_uint(hi)))
#define UNPACK2(lo, hi, a) do { unsigned _ul, _uh; \
    asm("mov.b64 {%0, %1}, %2;" : "=r"(_ul), "=r"(_uh) : "l"(a)); \
    lo = __uint_as_float(_ul); hi = __uint_as_float(_uh); } while (0)

// W relaid for packed r-pairs AND coalesced warp loads:
// g_W2[o], o = i*512 + jj*128 + c*4 + t  holds  W[i, c, q, r]
//   with q = (jj&1)*2 + (t>>1),  r = (jj>>1)*2 + (t&1)
// So lane c's float4 #jj = { wp[q][h], wp[q+1][h] } where wp[q][h] = {W[q][2h], W[q][2h+1]}.
__device__ float g_W2[KKI * NC * 16];

__global__ void relayout_W_kernel(const float* __restrict__ W) {
    int o = blockIdx.x * 256 + threadIdx.x;
    if (o < KKI * NC * 16) {
        int t  = o & 3;
        int c  = (o >> 2) & 31;
        int jj = (o >> 7) & 3;
        int i  = o >> 9;
        int q  = ((jj & 1) << 1) + (t >> 1);
        int r  = ((jj >> 1) << 1) + (t & 1);
        g_W2[o] = W[i * 512 + c * 16 + q * 4 + r];
    }
}

// Packed vote computation: vp[p*2+h] = {v[p][2h], v[p][2h+1]},  v[p][r] = sum_q m[p][q] * W[q][r]
__device__ __forceinline__ void compute_v(const float* __restrict__ sMpd, int i, int c, u64 vp[8]) {
    const ulonglong2* mp2 = reinterpret_cast<const ulonglong2*>(sMpd + i * 32);
    const ulonglong2* wb  = reinterpret_cast<const ulonglong2*>(g_W2 + i * 512) + c;
    ulonglong2 Wa = wb[0];   // h=0: q0,q1
    ulonglong2 Wb = wb[32];  // h=0: q2,q3
    ulonglong2 Wc = wb[64];  // h=1: q0,q1
    ulonglong2 Wd = wb[96];  // h=1: q2,q3
    #pragma unroll
    for (int p = 0; p < 4; p++) {
        ulonglong2 m01 = mp2[p * 2];      // {m[p][0]x2, m[p][1]x2}
        ulonglong2 m23 = mp2[p * 2 + 1];  // {m[p][2]x2, m[p][3]x2}
        u64 t0, t1;
        MUL2(t0, m23.y, Wb.y);
        FMA2(t0, m23.x, Wb.x, t0);
        FMA2(t0, m01.y, Wa.y, t0);
        FMA2(t0, m01.x, Wa.x, t0);
        vp[p * 2 + 0] = t0;
        MUL2(t1, m23.y, Wd.y);
        FMA2(t1, m23.x, Wd.x, t1);
        FMA2(t1, m01.y, Wc.y, t1);
        FMA2(t1, m01.x, Wc.x, t1);
        vp[p * 2 + 1] = t1;
    }
}

// Per-iteration statistics (scalar; lane = capsule c). Arrays stride 17.
__device__ __forceinline__ void compute_stats(
    const float* __restrict__ sAcc, const float* __restrict__ sS1, const float* __restrict__ sS2,
    int c, float rscale, float bv, float ba, float inv_temp,
    float M[16], float wgt[16], float& base, float& aj)
{
    float RsRaw = sAcc[c * 17 + 16];
    float Rs = RsRaw * rscale;
    float invR = 1.0f / RsRaw;
    float sumlog = 0.0f;
    #pragma unroll
    for (int k = 0; k < 16; k++) {
        float m   = sAcc[c * 17 + k] * invR;
        float var = sS2[c * 17 + k] - 2.0f * m * sS1[c * 17 + k] + 288.0f * m * m;
        var = fmaxf(var, 0.0f);
        float sd = sqrtf(var);
        sumlog += logf(sd + EPSV);
        wgt[k] = 0.5f / (sd * sd);
        M[k]   = m;
    }
    float cost = (16.0f * bv + sumlog) * Rs;
    float s = cost;
    #pragma unroll
    for (int o = 16; o >= 1; o >>= 1) s += __shfl_xor_sync(0xffffffffu, s, o);
    float cmean = s * (1.0f / 32.0f);
    float d = cost - cmean;
    float sq = d * d;
    #pragma unroll
    for (int o = 16; o >= 1; o >>= 1) sq += __shfl_xor_sync(0xffffffffu, sq, o);
    float cstd  = sqrtf(sq * (1.0f / 32.0f));
    float acost = ba + (cmean - cost) / (cstd + EPSV);
    aj   = 1.0f / (1.0f + expf(-inv_temp * acost));
    base = logf(aj + EPSV) - sumlog;
}

__global__ __launch_bounds__(NTH, 2)
void caps_em_kernel(const float* __restrict__ x,
                    const float* __restrict__ beta_v,
                    const float* __restrict__ beta_a,
                    float* __restrict__ out)
{
    __shared__ __align__(16) float sMpd[KKI * 32];  // duplicated poses: 9216 floats
    __shared__ __align__(16) float sAd[KKI * 2];    // duplicated activations: 576
    __shared__ float sAcc[NC * 17];                 // Mnum + Rsum
    __shared__ float sS1[NC * 17];                  // sum V
    __shared__ float sS2[NC * 17];                  // sum V^2

    const int tid  = threadIdx.x;
    const int c    = tid & 31;        // capsule
    const int wid  = tid >> 5;
    const int pos  = blockIdx.x;
    const int b  = pos / 144;
    const int rp = pos % 144;
    const int ho = rp / 12, wo = rp % 12;

    // ---- load patch (duplicated) ----
    for (int i = tid; i < KKI; i += NTH) {
        int kk = i >> 5, cin = i & 31;
        int ki = kk / 3, kj = kk % 3;
        const float* src = x + ((((b * 14) + ho + ki) * 14 + (wo + kj)) * 32 + cin) * 17;
        #pragma unroll
        for (int e = 0; e < 16; e++) {
            float v = src[e];
            sMpd[i * 32 + e * 2]     = v;
            sMpd[i * 32 + e * 2 + 1] = v;
        }
        float a = src[16];
        sAd[i * 2] = a; sAd[i * 2 + 1] = a;
    }
    for (int j = tid; j < NC * 17; j += NTH) { sAcc[j] = 0.0f; sS1[j] = 0.0f; sS2[j] = 0.0f; }
    __syncthreads();

    const float bv = beta_v[c];
    const float ba = beta_a[c];
    const int i0 = wid * IPW, i1 = i0 + IPW;
    const u64* sAd64 = reinterpret_cast<const u64*>(sAd);

    // ================= PASS 1: iter 0 (uniform R) + S1/S2 =================
    {
        u64 Mnum[8], S1[8], S2[8];
        float Rsum = 0.0f;
        #pragma unroll
        for (int j = 0; j < 8; j++) { Mnum[j] = 0ULL; S1[j] = 0ULL; S2[j] = 0ULL; }
        #pragma unroll 2
        for (int i = i0; i < i1; i++) {
            u64 vp[8];
            compute_v(sMpd, i, c, vp);
            u64 aip = sAd64[i];
            #pragma unroll
            for (int j = 0; j < 8; j++) {
                ADD2(S1[j], S1[j], vp[j]);
                FMA2(S2[j], vp[j], vp[j], S2[j]);
                FMA2(Mnum[j], aip, vp[j], Mnum[j]);
            }
            Rsum += __uint_as_float((unsigned)aip);
        }
        #pragma unroll
        for (int j = 0; j < 8; j++) {
            float l, h;
            UNPACK2(l, h, Mnum[j]); atomicAdd(&sAcc[c * 17 + 2 * j], l); atomicAdd(&sAcc[c * 17 + 2 * j + 1], h);
            UNPACK2(l, h, S1[j]);   atomicAdd(&sS1[c * 17 + 2 * j], l);  atomicAdd(&sS1[c * 17 + 2 * j + 1], h);
            UNPACK2(l, h, S2[j]);   atomicAdd(&sS2[c * 17 + 2 * j], l);  atomicAdd(&sS2[c * 17 + 2 * j + 1], h);
        }
        atomicAdd(&sAcc[c * 17 + 16], Rsum);
    }
    __syncthreads();

    float M[16], wgt[16], base, aj;
    compute_stats(sAcc, sS1, sS2, c, 1.0f / 32.0f, bv, ba, 1.0f, M, wgt, base, aj);
    u64 nMp[8], wgtp[8];
    #pragma unroll
    for (int j = 0; j < 8; j++) {
        PACK2(nMp[j], -M[2 * j], -M[2 * j + 1]);
        PACK2(wgtp[j], wgt[2 * j], wgt[2 * j + 1]);
    }
    __syncthreads();
    for (int j = tid; j < NC * 17; j += NTH) sAcc[j] = 0.0f;
    __syncthreads();

    // ================= PASS 2 & 3: routing iterations 1, 2 =================
    #pragma unroll 1
    for (int it = 1; it <= 2; it++) {
        u64 Mnum[8];
        float Rsum = 0.0f;
        #pragma unroll
        for (int j = 0; j < 8; j++) Mnum[j] = 0ULL;

        #pragma unroll 2
        for (int i = i0; i < i1; i++) {
            u64 vp[8];
            compute_v(sMpd, i, c, vp);
            u64 ep = 0ULL;
            #pragma unroll
            for (int j = 0; j < 8; j++) {
                u64 d, dw;
                ADD2(d, vp[j], nMp[j]);      // v - M
                MUL2(dw, d, wgtp[j]);
                FMA2(ep, dw, d, ep);
            }
            float el, eh;
            UNPACK2(el, eh, ep);
            float lp = base - (el + eh);
            // softmax over capsules (lanes)
            float mx = lp;
            #pragma unroll
            for (int o = 16; o >= 1; o >>= 1) mx = fmaxf(mx, __shfl_xor_sync(0xffffffffu, mx, o));
            float ex = __expf(lp - mx);
            float sm = ex;
            #pragma unroll
            for (int o = 16; o >= 1; o >>= 1) sm += __shfl_xor_sync(0xffffffffu, sm, o);
            float Rw = __uint_as_float((unsigned)sAd64[i]) * __fdividef(ex, sm);
            Rsum += Rw;
            u64 Rwp;
            PACK2(Rwp, Rw, Rw);
            #pragma unroll
            for (int j = 0; j < 8; j++) FMA2(Mnum[j], Rwp, vp[j], Mnum[j]);
        }
        #pragma unroll
        for (int j = 0; j < 8; j++) {
            float l, h;
            UNPACK2(l, h, Mnum[j]);
            atomicAdd(&sAcc[c * 17 + 2 * j], l);
            atomicAdd(&sAcc[c * 17 + 2 * j + 1], h);
        }
        atomicAdd(&sAcc[c * 17 + 16], Rsum);
        __syncthreads();

        compute_stats(sAcc, sS1, sS2, c, 1.0f, bv, ba, 1.0f + (float)it, M, wgt, base, aj);
        if (it < 2) {
            #pragma unroll
            for (int j = 0; j < 8; j++) {
                PACK2(nMp[j], -M[2 * j], -M[2 * j + 1]);
                PACK2(wgtp[j], wgt[2 * j], wgt[2 * j + 1]);
            }
            __syncthreads();
            for (int j = tid; j < NC * 17; j += NTH) sAcc[j] = 0.0f;
            __syncthreads();
        }
    }

    // ---- write output: [pos][c][0..15] = M, [16] = sigmoid(a_j) ----
    if (wid == 0) {
        float* dst = out + (pos * NC + c) * 17;
        #pragma unroll
        for (int k = 0; k < 16; k++) dst[k] = M[k];
        dst[16] = 1.0f / (1.0f + expf(-aj));
    }
}

extern "C" void kernel_launch(void* const* d_in, const int* in_sizes, int n_in,
                              void* d_out, int out_size) {
    const float* x      = (const float*)d_in[0];
    const float* W      = (const float*)d_in[1];
    const float* beta_v = (const float*)d_in[2];
    const float* beta_a = (const float*)d_in[3];
    float* out = (float*)d_out;

    relayout_W_kernel<<<(KKI * NC * 16 + 255) / 256, 256>>>(W);
    caps_em_kernel<<<NPOS, NTH>>>(x, beta_v, beta_a, out);
}

// round 7
// speedup vs baseline: 1.1812x; 1.1812x over previous
#include <cuda_runtime.h>

#define EPSV 1e-7f
#define NPOS 288     // 2*12*12 output positions
#define KKI  288     // 3*3*32 input votes
#define NC   32
#define PP   16
#define NTH  256
#define NWARP 8
#define IPW  36      // KKI / NWARP

__device__ __forceinline__ float bfly_max(float v) {
    #pragma unroll
    for (int o = 16; o >= 1; o >>= 1) v = fmaxf(v, __shfl_xor_sync(0xffffffffu, v, o));
    return v;
}
__device__ __forceinline__ float bfly_sum(float v) {
    #pragma unroll
    for (int o = 16; o >= 1; o >>= 1) v += __shfl_xor_sync(0xffffffffu, v, o);
    return v;
}

// W re-laid out chunk-major for coalesced warp loads:
// g_W2[i][j][c][q]  (j = output-column chunk r, c = capsule, q fastest)
__device__ float g_W2[KKI * NC * PP];

__global__ void relayout_W_kernel(const float* __restrict__ W) {
    int o = blockIdx.x * 256 + threadIdx.x;
    if (o < KKI * NC * PP) {
        int q = o & 3;
        int c = (o >> 2) & 31;
        int j = (o >> 7) & 3;
        int i = o >> 9;
        g_W2[o] = W[i * 512 + c * 16 + q * 4 + j];
    }
}

__device__ __forceinline__ float dot4(float4 a, float4 b) {
    return fmaf(a.x, b.x, fmaf(a.y, b.y, fmaf(a.z, b.z, a.w * b.w)));
}

// Compute V[i, c, 0..15] for this thread's capsule c (coalesced: 4 wf per LDG).
__device__ __forceinline__ void compute_v(const float* __restrict__ sMp, int i, int c, float v[16]) {
    const float4* mp = reinterpret_cast<const float4*>(sMp + i * 16);
    float4 m0 = mp[0], m1 = mp[1], m2 = mp[2], m3 = mp[3];
    const float4* wp = reinterpret_cast<const float4*>(g_W2 + i * 512) + c;
    float4 w0 = wp[0], w1 = wp[32], w2 = wp[64], w3 = wp[96];
    v[0]  = dot4(m0, w0); v[1]  = dot4(m0, w1); v[2]  = dot4(m0, w2); v[3]  = dot4(m0, w3);
    v[4]  = dot4(m1, w0); v[5]  = dot4(m1, w1); v[6]  = dot4(m1, w2); v[7]  = dot4(m1, w3);
    v[8]  = dot4(m2, w0); v[9]  = dot4(m2, w1); v[10] = dot4(m2, w2); v[11] = dot4(m2, w3);
    v[12] = dot4(m3, w0); v[13] = dot4(m3, w1); v[14] = dot4(m3, w2); v[15] = dot4(m3, w3);
}

// Per-iteration statistics. sRedM stride 17; sRedS stride 33.
__device__ __forceinline__ void compute_stats(
    const float* __restrict__ sRedM, const float* __restrict__ sRedS,
    int c, float rscale, float bv, float ba, float inv_temp,
    float M[16], float wgt[16], float& base, float& aj)
{
    float RsRaw = sRedM[c * 17 + 16];
    float Rs = RsRaw * rscale;
    float invR = __fdividef(1.0f, RsRaw);
    float sumlog = 0.0f;
    #pragma unroll
    for (int k = 0; k < 16; k++) {
        float m   = sRedM[c * 17 + k] * invR;
        float s1  = sRedS[c * 33 + k];
        float s2  = sRedS[c * 33 + 16 + k];
        float var = s2 - 2.0f * m * s1 + 288.0f * m * m;
        var = fmaxf(var, 0.0f);
        float sd = sqrtf(var);
        sumlog += __logf(sd + EPSV);
        wgt[k] = __fdividef(0.5f, sd * sd + 1e-30f);
        M[k]   = m;
    }
    float cost = (16.0f * bv + sumlog) * Rs;
    float cmean = bfly_sum(cost) * (1.0f / 32.0f);
    float d = cost - cmean;
    float cstd = sqrtf(bfly_sum(d * d) * (1.0f / 32.0f));
    float acost = ba + __fdividef(cmean - cost, cstd + EPSV);
    aj   = __fdividef(1.0f, 1.0f + __expf(-inv_temp * acost));
    base = __logf(aj + EPSV) - sumlog;
}

__global__ __launch_bounds__(NTH, 2)
void caps_em_kernel(const float* __restrict__ x,
                    const float* __restrict__ beta_v,
                    const float* __restrict__ beta_a,
                    float* __restrict__ out)
{
    __shared__ float sMp[KKI * 16];          // 4608 floats
    __shared__ float sA[KKI];                // 288
    __shared__ float sPart[NWARP * NC * 17]; // 4352
    __shared__ float sRedM[NC * 17];         // 544
    __shared__ float sRedS[NC * 33];         // 1056

    const int tid  = threadIdx.x;
    const int c    = tid & 31;        // capsule
    const int wid  = tid >> 5;
    const int pos  = blockIdx.x;
    const int b  = pos / 144;
    const int rp = pos % 144;
    const int ho = rp / 12, wo = rp % 12;

    // ---- load patch: i = (ki*3+kj)*32 + cin ----
    for (int i = tid; i < KKI; i += NTH) {
        int kk = i >> 5, cin = i & 31;
        int ki = kk / 3, kj = kk % 3;
        const float* src = x + ((((b * 14) + ho + ki) * 14 + (wo + kj)) * 32 + cin) * 17;
        #pragma unroll
        for (int e = 0; e < 16; e++) sMp[i * 16 + e] = src[e];
        sA[i] = src[16];
    }
    __syncthreads();

    const float bv = beta_v[c];
    const float ba = beta_a[c];
    const int i0 = wid * IPW, i1 = i0 + IPW;
    float* myP = sPart + (wid * NC + c) * 17;

    // ================= PASS 1: iter 0 (uniform R) + S1/S2 =================
    {
        float Mnum[16], S1[16], S2[16];
        float Rsum = 0.0f;
        #pragma unroll
        for (int k = 0; k < 16; k++) { Mnum[k] = 0.0f; S1[k] = 0.0f; S2[k] = 0.0f; }
        #pragma unroll 2
        for (int i = i0; i < i1; i++) {
            float v[16];
            compute_v(sMp, i, c, v);
            float ai = sA[i];
            #pragma unroll
            for (int k = 0; k < 16; k++) {
                S1[k] += v[k];
                S2[k]  = fmaf(v[k], v[k], S2[k]);
                Mnum[k] = fmaf(ai, v[k], Mnum[k]);
            }
            Rsum += ai;
        }
        // --- round A: Mnum + Rsum ---
        #pragma unroll
        for (int k = 0; k < 16; k++) myP[k] = Mnum[k];
        myP[16] = Rsum;
        __syncthreads();
        for (int s = tid; s < NC * 17; s += NTH) {
            float acc = 0.0f;
            #pragma unroll
            for (int w = 0; w < NWARP; w++) acc += sPart[w * (NC * 17) + s];
            sRedM[s] = acc;
        }
        __syncthreads();
        // --- round B: S1 ---
        #pragma unroll
        for (int k = 0; k < 16; k++) myP[k] = S1[k];
        __syncthreads();
        for (int s = tid; s < NC * 17; s += NTH) {
            int cc = s / 17, kk = s - cc * 17;
            if (kk < 16) {
                float acc = 0.0f;
                #pragma unroll
                for (int w = 0; w < NWARP; w++) acc += sPart[w * (NC * 17) + s];
                sRedS[cc * 33 + kk] = acc;
            }
        }
        __syncthreads();
        // --- round C: S2 ---
        #pragma unroll
        for (int k = 0; k < 16; k++) myP[k] = S2[k];
        __syncthreads();
        for (int s = tid; s < NC * 17; s += NTH) {
            int cc = s / 17, kk = s - cc * 17;
            if (kk < 16) {
                float acc = 0.0f;
                #pragma unroll
                for (int w = 0; w < NWARP; w++) acc += sPart[w * (NC * 17) + s];
                sRedS[cc * 33 + 16 + kk] = acc;
            }
        }
        __syncthreads();
    }

    float M[16], wgt[16], base, aj;
    compute_stats(sRedM, sRedS, c, 1.0f / 32.0f, bv, ba, 1.0f, M, wgt, base, aj);

    // Folded Mahalanobis coefficients: e_orig = sum wgt*(v-M)^2
    //   lp = base - e_orig = baseAdj - sum_k (wgt*v + m2)*v,  m2 = -2*wgt*M, baseAdj = base - sum wgt*M^2
    float m2[16], baseAdj, bmax;
    {
        float cM = 0.0f;
        #pragma unroll
        for (int k = 0; k < 16; k++) { m2[k] = -2.0f * wgt[k] * M[k]; cM = fmaf(wgt[k] * M[k], M[k], cM); }
        baseAdj = base - cM;
        bmax = bfly_max(base);   // lane-uniform upper bound on lp (e_orig >= 0)
    }

    // ================= PASS 2 & 3: routing iterations 1, 2 =================
    #pragma unroll 1
    for (int it = 1; it <= 2; it++) {
        float Mnum[16];
        float Rsum = 0.0f;
        #pragma unroll
        for (int k = 0; k < 16; k++) Mnum[k] = 0.0f;

        #pragma unroll 2
        for (int i = i0; i < i1; i++) {
            float v[16];
            compute_v(sMp, i, c, v);
            float e = 0.0f;
            #pragma unroll
            for (int k = 0; k < 16; k++) {
                float t = fmaf(wgt[k], v[k], m2[k]);
                e = fmaf(t, v[k], e);
            }
            float lp = baseAdj - e;
            // softmax over capsules (lanes): uniform-shift by bmax, single sum reduction
            float ex = __expf(lp - bmax);
            float sm = bfly_sum(ex) + 1e-38f;
            float Rw = sA[i] * __fdividef(ex, sm);
            Rsum += Rw;
            #pragma unroll
            for (int k = 0; k < 16; k++) Mnum[k] = fmaf(Rw, v[k], Mnum[k]);
        }
        __syncthreads();  // protect sPart reuse from previous round's readers
        #pragma unroll
        for (int k = 0; k < 16; k++) myP[k] = Mnum[k];
        myP[16] = Rsum;
        __syncthreads();
        for (int s = tid; s < NC * 17; s += NTH) {
            float acc = 0.0f;
            #pragma unroll
            for (int w = 0; w < NWARP; w++) acc += sPart[w * (NC * 17) + s];
            sRedM[s] = acc;
        }
        __syncthreads();

        compute_stats(sRedM, sRedS, c, 1.0f, bv, ba, 1.0f + (float)it, M, wgt, base, aj);
        if (it < 2) {
            float cM = 0.0f;
            #pragma unroll
            for (int k = 0; k < 16; k++) { m2[k] = -2.0f * wgt[k] * M[k]; cM = fmaf(wgt[k] * M[k], M[k], cM); }
            baseAdj = base - cM;
            bmax = bfly_max(base);
        }
    }

    // ---- write output: [pos][c][0..15] = M, [16] = sigmoid(a_j) ----
    if (wid == 0) {
        float* dst = out + (pos * NC + c) * 17;
        #pragma unroll
        for (int k = 0; k < 16; k++) dst[k] = M[k];
        dst[16] = __fdividef(1.0f, 1.0f + __expf(-aj));
    }
}

extern "C" void kernel_launch(void* const* d_in, const int* in_sizes, int n_in,
                              void* d_out, int out_size) {
    const float* x      = (const float*)d_in[0];
    const float* W      = (const float*)d_in[1];
    const float* beta_v = (const float*)d_in[2];
    const float* beta_a = (const float*)d_in[3];
    float* out = (float*)d_out;

    relayout_W_kernel<<<(KKI * NC * PP + 255) / 256, 256>>>(W);
    caps_em_kernel<<<NPOS, NTH>>>(x, beta_v, beta_a, out);
}